// round 11
// baseline (speedup 1.0000x reference)
#include <cuda_runtime.h>
#include <cuda_bf16.h>
#include <cstdint>
#include <math.h>

#define B_ 4
#define N_ 4096
#define D_ 1024
#define G_ 4
#define H_ 8
#define DH_ 64
#define DI_ 512
#define NQ_ 1024
#define NK_ 512
#define NKV_ 513
#define NKVP_ 576

// ---------------- scratch ---------------------------------------------------
__device__ float         g_qlog [B_*G_*N_];
__device__ float         g_kvlog[B_*G_*N_];
__device__ int           g_qidx [B_*G_*NQ_];
__device__ float         g_qscore[B_*G_*NQ_];
__device__ int           g_kvidx [B_*G_*NK_];
__device__ float         g_sscale[B_*G_*NKVP_];
__device__ int           g_slot [B_*G_*N_];
__device__ __nv_bfloat16 g_xbf  [B_*N_*D_];
__device__ __nv_bfloat16 g_wqbf [G_*DI_*D_];
__device__ __nv_bfloat16 g_wkvbf[G_*2*DI_*D_];
__device__ __nv_bfloat16 g_woutbf[G_*D_*DI_];
__device__ __nv_bfloat16 g_nullbf[2*G_*H_*DH_];
__device__ __nv_bfloat16 g_q    [B_*G_*NQ_*DI_];
__device__ __nv_bfloat16 g_kv   [B_*G_*NK_*2*DI_];
__device__ __nv_bfloat16 g_attno[B_*G_*NQ_*DI_];
__device__ float         g_of   [(size_t)B_*G_*NQ_*D_];

// ---------------- helpers ---------------------------------------------------
__device__ __forceinline__ uint32_t f2bf2(float lo, float hi) {
    uint32_t r;
    asm("cvt.rn.bf16x2.f32 %0, %1, %2;" : "=r"(r) : "f"(hi), "f"(lo));
    return r;
}
__device__ __forceinline__ void mma_bf16(float c[4],
                                         uint32_t a0, uint32_t a1, uint32_t a2, uint32_t a3,
                                         uint32_t b0, uint32_t b1) {
    asm volatile(
        "mma.sync.aligned.m16n8k16.row.col.f32.bf16.bf16.f32 "
        "{%0,%1,%2,%3}, {%4,%5,%6,%7}, {%8,%9}, {%0,%1,%2,%3};\n"
        : "+f"(c[0]), "+f"(c[1]), "+f"(c[2]), "+f"(c[3])
        : "r"(a0), "r"(a1), "r"(a2), "r"(a3), "r"(b0), "r"(b1));
}
__device__ __forceinline__ void ldsm_x4(uint32_t& r0, uint32_t& r1, uint32_t& r2, uint32_t& r3,
                                        uint32_t addr) {
    asm volatile("ldmatrix.sync.aligned.m8n8.x4.shared.b16 {%0,%1,%2,%3}, [%4];"
                 : "=r"(r0), "=r"(r1), "=r"(r2), "=r"(r3) : "r"(addr));
}
__device__ __forceinline__ void ldsm_x4_t(uint32_t& r0, uint32_t& r1, uint32_t& r2, uint32_t& r3,
                                          uint32_t addr) {
    asm volatile("ldmatrix.sync.aligned.m8n8.x4.trans.shared.b16 {%0,%1,%2,%3}, [%4];"
                 : "=r"(r0), "=r"(r1), "=r"(r2), "=r"(r3) : "r"(addr));
}
__device__ __forceinline__ void cp_async16(void* smem_dst, const void* gmem_src) {
    uint32_t s = (uint32_t)__cvta_generic_to_shared(smem_dst);
    asm volatile("cp.async.cg.shared.global [%0], [%1], 16;\n" :: "r"(s), "l"(gmem_src));
}
__device__ __forceinline__ void cp_commit() { asm volatile("cp.async.commit_group;\n"); }
__device__ __forceinline__ void cp_wait0() { asm volatile("cp.async.wait_group 0;\n"); }
__device__ __forceinline__ void cp_wait1() { asm volatile("cp.async.wait_group 1;\n"); }
__device__ __forceinline__ void cp_wait2() { asm volatile("cp.async.wait_group 2;\n"); }

// ---------------- 0) fp32 -> bf16 convert (weights + null_kv) ---------------
#define WQ4   (G_*DI_*D_/4)
#define WKV4  (G_*2*DI_*D_/4)
#define WOUT4 (G_*D_*DI_/4)
#define NUL4  (2*G_*H_*DH_/4)
__device__ __forceinline__ void cvt4(const float* s, __nv_bfloat16* d, int i) {
    float4 v = ((const float4*)s)[i];
    ((uint2*)d)[i] = make_uint2(f2bf2(v.x, v.y), f2bf2(v.z, v.w));
}
__global__ void cvt_all(const float* __restrict__ wq, const float* __restrict__ wkv,
                        const float* __restrict__ wout, const float* __restrict__ nul)
{
    int i = blockIdx.x*256 + threadIdx.x;
    if (i < WQ4) { cvt4(wq, g_wqbf, i); return; }
    i -= WQ4;
    if (i < WKV4) { cvt4(wkv, g_wkvbf, i); return; }
    i -= WKV4;
    if (i < WOUT4) { cvt4(wout, g_woutbf, i); return; }
    i -= WOUT4;
    if (i < NUL4) cvt4(nul, g_nullbf, i);
}

// ---------------- 1) router logits (fp32) + x -> bf16 -----------------------
__global__ void __launch_bounds__(512) logits_kernel(const float* __restrict__ x,
                                                     const float* __restrict__ w_qr,
                                                     const float* __restrict__ w_kvr)
{
    __shared__ float ws[8*D_];
    int tid = threadIdx.x;
    for (int i = tid; i < 4*D_; i += 512) { ws[i] = w_qr[i]; ws[4*D_+i] = w_kvr[i]; }
    __syncthreads();
    int warp = tid >> 5, lane = tid & 31;
    int tok = blockIdx.x*16 + warp;
    int b = tok / N_, n = tok % N_;
    const float4* xr = (const float4*)(x + (size_t)tok*D_);
    uint2* xt = (uint2*)(g_xbf + (size_t)tok*D_);
    float acc[8] = {0,0,0,0,0,0,0,0};
    #pragma unroll
    for (int it = 0; it < 8; it++) {
        int k4 = lane + it*32;
        float4 xv = xr[k4];
        xt[k4] = make_uint2(f2bf2(xv.x, xv.y), f2bf2(xv.z, xv.w));
        #pragma unroll
        for (int g = 0; g < 8; g++) {
            const float* w = ws + g*D_ + k4*4;
            acc[g] += xv.x*w[0] + xv.y*w[1] + xv.z*w[2] + xv.w*w[3];
        }
    }
    #pragma unroll
    for (int g = 0; g < 8; g++) {
        #pragma unroll
        for (int o = 16; o > 0; o >>= 1) acc[g] += __shfl_xor_sync(0xffffffffu, acc[g], o);
    }
    if (lane < 4) {
        g_qlog[(b*G_+lane)*N_ + n] = acc[lane];
        g_slot[(b*G_+lane)*N_ + n] = -1;
    } else if (lane < 8) {
        g_kvlog[(b*G_+(lane-4))*N_ + n] = acc[lane];
    }
}

// ---------------- 2) exact top-k via per-(b,g) bitonic sort (q + kv) --------
__global__ void topk_kernel()
{
    __shared__ float sv[N_];
    __shared__ int   si[N_];
    const bool isq = blockIdx.x < (B_*G_);
    const int bg = isq ? blockIdx.x : blockIdx.x - B_*G_;
    const int ksel = isq ? NQ_ : NK_;
    const float* L = (isq ? g_qlog : g_kvlog) + (size_t)bg*N_;
    for (int i = threadIdx.x; i < N_; i += blockDim.x) { sv[i]=L[i]; si[i]=i; }
    __syncthreads();
    for (int k = 2; k <= N_; k <<= 1) {
        for (int j = k>>1; j > 0; j >>= 1) {
            for (int t = threadIdx.x; t < N_/2; t += blockDim.x) {
                int i = ((t / j) * (2*j)) + (t % j);
                int p = i | j;
                bool descend = ((i & k) == 0);
                float va = sv[i], vb = sv[p];
                int   ia = si[i], ib = si[p];
                bool agtb = (va > vb) || (va == vb && ia < ib);
                if (agtb != descend) { sv[i]=vb; si[i]=ib; sv[p]=va; si[p]=ia; }
            }
            __syncthreads();
        }
    }
    if (isq) {
        for (int i = threadIdx.x; i < ksel; i += blockDim.x) {
            int id = si[i];
            g_qidx[bg*ksel + i]   = id;
            g_qscore[bg*ksel + i] = 1.0f/(1.0f + expf(-sv[i]));
            g_slot[(size_t)bg*N_ + id] = i;
        }
    } else {
        for (int i = threadIdx.x; i < ksel; i += blockDim.x) {
            g_kvidx[bg*ksel + i] = si[i];
            g_sscale[bg*NKVP_ + 1 + i] = 1.0f/(1.0f + expf(-sv[i]));
        }
        if (threadIdx.x == 0) g_sscale[bg*NKVP_] = 1.0f;
        for (int i = NKV_ + threadIdx.x; i < NKVP_; i += blockDim.x)
            g_sscale[bg*NKVP_ + i] = 1.0f;
    }
}

// ---------------- 3) 3-stage cp.async bf16 GEMM, 2 CTA/SM -------------------
// BM=128, BN=128, BK=32(bf16), 8 warps (2x4), warp tile 64x32, ldmatrix frags.
template<int BM,int BN,int BK,bool GATHER,bool OUT_BF16>
__global__ void __launch_bounds__(256, 2)
mma_gemm(const __nv_bfloat16* __restrict__ A, int lda, int zdivA, long sA1, long sA2,
         const __nv_bfloat16* __restrict__ Bp, int ldb, int zdivB, long sB1, long sB2,
         void* __restrict__ Cv, int ldc, int zdivC, long sC1, long sC2,
         int K,
         const int* __restrict__ gidx, int gstride,
         const float* __restrict__ rowScale, int rsStride,
         float cscale)
{
    constexpr int WM = BM/2, WN = BN/4;      // 64, 32
    constexpr int MI = WM/16, NI = WN/8;     // 4, 4
    constexpr int BKP2 = BK/2 + 4;           // 20 b32 row stride
    constexpr int ASTG = BM*BKP2, BSTG = BN*BKP2;

    extern __shared__ uint32_t dsm[];
    uint32_t* Asf = dsm;                      // 3 stages
    uint32_t* Bsf = dsm + 3*ASTG;
    int*      ridx = (int*)(dsm + 3*ASTG + 3*BSTG);

    const int z = blockIdx.z;
    A  += (long)(z/zdivA)*sA1 + (long)(z%zdivA)*sA2;
    Bp += (long)(z/zdivB)*sB1 + (long)(z%zdivB)*sB2;
    const int m0 = blockIdx.y*BM, n0 = blockIdx.x*BN;
    const int tid  = threadIdx.x;
    const int warp = tid >> 5, lane = tid & 31;
    const int gid  = lane >> 2, tig = lane & 3;
    const int wm0  = (warp >> 2) * WM;
    const int wn0  = (warp & 3) * WN;

    if (GATHER) {
        for (int i = tid; i < BM; i += 256) ridx[i] = gidx[z*gstride + m0 + i];
        __syncthreads();
    }

    auto prefetch = [&](int k0, int s) {
        uint32_t* As_ = Asf + s*ASTG;
        #pragma unroll
        for (int f = tid; f < BM*(BK/8); f += 256) {
            int m = f / (BK/8), c = f % (BK/8);
            long row = GATHER ? (long)ridx[m] : (long)(m0+m);
            cp_async16(&As_[m*BKP2 + c*4], A + row*(long)lda + k0 + c*8);
        }
        uint32_t* Bs_ = Bsf + s*BSTG;
        #pragma unroll
        for (int f = tid; f < BN*(BK/8); f += 256) {
            int nn = f / (BK/8), c = f % (BK/8);
            cp_async16(&Bs_[nn*BKP2 + c*4], Bp + (long)(n0+nn)*ldb + k0 + c*8);
        }
        cp_commit();
    };

    float acc[MI][NI][4];
    #pragma unroll
    for (int mi=0;mi<MI;mi++)
        #pragma unroll
        for (int ni=0;ni<NI;ni++)
            #pragma unroll
            for (int r=0;r<4;r++) acc[mi][ni][r] = 0.f;

    const uint32_t AsA = (uint32_t)__cvta_generic_to_shared(Asf);
    const uint32_t BsA = (uint32_t)__cvta_generic_to_shared(Bsf);
    const int lm = lane >> 3, lr = lane & 7;
    const uint32_t aLane = (uint32_t)(((wm0 + (lm&1)*8 + lr)*BKP2 + (lm>>1)*4) * 4);
    const uint32_t bLane = (uint32_t)(((wn0 + (lm>>1)*8 + lr)*BKP2 + (lm&1)*4) * 4);

    const int NKIT = K / BK;
    prefetch(0, 0);
    if (NKIT > 1) prefetch(BK, 1);
    for (int j = 0; j < NKIT; j++) {
        if (j + 2 < NKIT) { prefetch((j+2)*BK, (j+2)%3); cp_wait2(); }
        else if (j + 1 < NKIT) { cp_wait1(); }
        else { cp_wait0(); }
        __syncthreads();

        const uint32_t AsJ = AsA + (uint32_t)((j%3)*ASTG*4) + aLane;
        const uint32_t BsJ = BsA + (uint32_t)((j%3)*BSTG*4) + bLane;
        #pragma unroll
        for (int kk = 0; kk < BK/16; kk++) {
            uint32_t a[MI][4];
            uint32_t b[NI][2];
            #pragma unroll
            for (int mi=0;mi<MI;mi++)
                ldsm_x4(a[mi][0], a[mi][1], a[mi][2], a[mi][3],
                        AsJ + (uint32_t)(mi*16*BKP2*4 + kk*32));
            #pragma unroll
            for (int nip=0;nip<NI/2;nip++)
                ldsm_x4(b[2*nip][0], b[2*nip][1], b[2*nip+1][0], b[2*nip+1][1],
                        BsJ + (uint32_t)(nip*16*BKP2*4 + kk*32));
            #pragma unroll
            for (int mi=0;mi<MI;mi++)
                #pragma unroll
                for (int ni=0;ni<NI;ni++)
                    mma_bf16(acc[mi][ni], a[mi][0], a[mi][1], a[mi][2], a[mi][3],
                             b[ni][0], b[ni][1]);
        }
        __syncthreads();
    }

    #pragma unroll
    for (int mi=0;mi<MI;mi++) {
        int r0 = m0 + wm0 + mi*16 + gid;
        int r1 = r0 + 8;
        float rs0 = cscale, rs1 = cscale;
        if (rowScale) {
            rs0 *= rowScale[z*rsStride + r0];
            rs1 *= rowScale[z*rsStride + r1];
        }
        #pragma unroll
        for (int ni=0;ni<NI;ni++) {
            int ccol = n0 + wn0 + ni*8 + tig*2;
            if (OUT_BF16) {
                uint32_t* Cb = (uint32_t*)Cv + ((long)(z/zdivC)*sC1 + (long)(z%zdivC)*sC2)/2;
                Cb[((long)r0*ldc + ccol) >> 1] = f2bf2(acc[mi][ni][0]*rs0, acc[mi][ni][1]*rs0);
                Cb[((long)r1*ldc + ccol) >> 1] = f2bf2(acc[mi][ni][2]*rs1, acc[mi][ni][3]*rs1);
            } else {
                float* C = (float*)Cv + (long)(z/zdivC)*sC1 + (long)(z%zdivC)*sC2;
                *(float2*)(C + (long)r0*ldc + ccol) =
                    make_float2(acc[mi][ni][0]*rs0, acc[mi][ni][1]*rs0);
                *(float2*)(C + (long)r1*ldc + ccol) =
                    make_float2(acc[mi][ni][2]*rs1, acc[mi][ni][3]*rs1);
            }
        }
    }
}

// ---------------- 4) fused flash attention: exp-direct softmax --------------
#define KR2 36
__global__ void __launch_bounds__(256) attn_kernel(int bghOff)
{
    extern __shared__ uint32_t smem[];
    uint32_t* Ks = smem;
    uint32_t* Vs = smem + 2*64*KR2;
    float*    Ss = (float*)(smem + 4*64*KR2);

    const int bgh = blockIdx.y + bghOff;
    const int bg = bgh >> 3, h = bgh & 7;
    const int g  = bg & 3;
    const int m0q = blockIdx.x * 128;
    const int tid = threadIdx.x, warp = tid >> 5, lane = tid & 31;
    const int gid = lane >> 2, tig = lane & 3;
    const int wm = warp * 16;

    const __nv_bfloat16* Qbase = g_q + (size_t)bg*NQ_*DI_ + h*DH_;
    const __nv_bfloat16* KVb   = g_kv + (size_t)bg*NK_*2*DI_ + h*DH_;
    const __nv_bfloat16* nulK  = g_nullbf + ((0*G_+g)*H_ + h)*DH_;
    const __nv_bfloat16* nulV  = g_nullbf + ((1*G_+g)*H_ + h)*DH_;
    const float*         Sg    = g_sscale + bg*NKVP_;

    const int r0 = m0q + wm + gid, r1 = r0 + 8;

    auto prefetch = [&](int ch, int s) {
        const int j0 = ch * 64;
        uint32_t* Kd = Ks + s*64*KR2;
        uint32_t* Vd = Vs + s*64*KR2;
        #pragma unroll
        for (int f = tid; f < 64*8; f += 256) {
            int r = f >> 3, c = (f & 7) * 8;
            int j = j0 + r;
            if (j == 0) {
                cp_async16(&Kd[r*KR2 + c/2], nulK + c);
                cp_async16(&Vd[r*KR2 + c/2], nulV + c);
            } else {
                int jj = (j-1 < NK_-1) ? (j-1) : (NK_-1);
                const __nv_bfloat16* base = KVb + (size_t)jj*(2*DI_) + c;
                cp_async16(&Kd[r*KR2 + c/2], base);
                cp_async16(&Vd[r*KR2 + c/2], base + DI_);
            }
        }
        if (tid < 16) cp_async16(&Ss[s*64 + tid*4], Sg + j0 + tid*4);
        cp_commit();
    };

    uint32_t aQ[4][4];
    #pragma unroll
    for (int kk = 0; kk < 4; kk++) {
        aQ[kk][0] = *(const uint32_t*)(Qbase + (size_t)r0*DI_ + kk*16 + 2*tig    );
        aQ[kk][1] = *(const uint32_t*)(Qbase + (size_t)r1*DI_ + kk*16 + 2*tig    );
        aQ[kk][2] = *(const uint32_t*)(Qbase + (size_t)r0*DI_ + kk*16 + 2*tig + 8);
        aQ[kk][3] = *(const uint32_t*)(Qbase + (size_t)r1*DI_ + kk*16 + 2*tig + 8);
    }

    const int lm = lane >> 3, lr = lane & 7;
    const uint32_t kLane = (uint32_t)((((lm>>1)*8 + lr)*KR2 + (lm&1)*4) * 4);
    const uint32_t vLane = (uint32_t)(((lm & 1)*8 + lr) * (KR2*4) + (lm >> 1)*16);
    const uint32_t KsA = (uint32_t)__cvta_generic_to_shared(Ks);
    const uint32_t VsA = (uint32_t)__cvta_generic_to_shared(Vs);

    float o[8][4];
    #pragma unroll
    for (int i=0;i<8;i++) { o[i][0]=0.f; o[i][1]=0.f; o[i][2]=0.f; o[i][3]=0.f; }
    float l0 = 0.f, l1 = 0.f;

    prefetch(0, 0);
    for (int ch = 0; ch < 9; ch++) {
        const int s = ch & 1;
        const int j0 = ch * 64;
        if (ch < 8) { prefetch(ch+1, s^1); cp_wait1(); }
        else        { cp_wait0(); }
        __syncthreads();
        const uint32_t KcA = KsA + (uint32_t)(s*64*KR2*4) + kLane;
        const uint32_t VcA = VsA + (uint32_t)(s*64*KR2*4) + vLane;
        const float*   sc  = Ss + s*64;

        float sfr[8][4];
        #pragma unroll
        for (int i=0;i<8;i++){ sfr[i][0]=0.f; sfr[i][1]=0.f; sfr[i][2]=0.f; sfr[i][3]=0.f; }
        #pragma unroll
        for (int kk = 0; kk < 4; kk++) {
            #pragma unroll
            for (int nip = 0; nip < 4; nip++) {
                uint32_t b0, b1, b2, b3;
                ldsm_x4(b0, b1, b2, b3, KcA + (uint32_t)(nip*16*KR2*4 + kk*32));
                mma_bf16(sfr[2*nip  ], aQ[kk][0], aQ[kk][1], aQ[kk][2], aQ[kk][3], b0, b1);
                mma_bf16(sfr[2*nip+1], aQ[kk][0], aQ[kk][1], aQ[kk][2], aQ[kk][3], b2, b3);
            }
        }
        if (ch == 8) {
            #pragma unroll
            for (int ni = 0; ni < 8; ni++) {
                int j = j0 + ni*8 + 2*tig;
                if (j   > 512) { sfr[ni][0] = -1e30f; sfr[ni][2] = -1e30f; }
                if (j+1 > 512) { sfr[ni][1] = -1e30f; sfr[ni][3] = -1e30f; }
            }
        }
        #pragma unroll
        for (int ni = 0; ni < 8; ni++) {
            sfr[ni][0] = __expf(sfr[ni][0]);
            sfr[ni][1] = __expf(sfr[ni][1]);
            sfr[ni][2] = __expf(sfr[ni][2]);
            sfr[ni][3] = __expf(sfr[ni][3]);
            l0 += sfr[ni][0] + sfr[ni][1];
            l1 += sfr[ni][2] + sfr[ni][3];
        }
        #pragma unroll
        for (int kk = 0; kk < 4; kk++) {
            float2 sA = *(const float2*)&sc[kk*16 + 2*tig    ];
            float2 sB = *(const float2*)&sc[kk*16 + 2*tig + 8];
            uint32_t aP0 = f2bf2(sfr[2*kk  ][0]*sA.x, sfr[2*kk  ][1]*sA.y);
            uint32_t aP1 = f2bf2(sfr[2*kk  ][2]*sA.x, sfr[2*kk  ][3]*sA.y);
            uint32_t aP2 = f2bf2(sfr[2*kk+1][0]*sB.x, sfr[2*kk+1][1]*sB.y);
            uint32_t aP3 = f2bf2(sfr[2*kk+1][2]*sB.x, sfr[2*kk+1][3]*sB.y);
            #pragma unroll
            for (int np = 0; np < 4; np++) {
                uint32_t v0, v1, v2, v3;
                ldsm_x4_t(v0, v1, v2, v3, VcA + (uint32_t)(kk*16*(KR2*4) + np*32));
                mma_bf16(o[2*np  ], aP0, aP1, aP2, aP3, v0, v1);
                mma_bf16(o[2*np+1], aP0, aP1, aP2, aP3, v2, v3);
            }
        }
        __syncthreads();
    }

    l0 += __shfl_xor_sync(0xffffffffu, l0, 1);
    l0 += __shfl_xor_sync(0xffffffffu, l0, 2);
    l1 += __shfl_xor_sync(0xffffffffu, l1, 1);
    l1 += __shfl_xor_sync(0xffffffffu, l1, 2);
    float i0 = 1.f/l0, i1 = 1.f/l1;
    __nv_bfloat16* Obase = g_attno + (size_t)bg*NQ_*DI_ + h*DH_;
    #pragma unroll
    for (int ni2 = 0; ni2 < 8; ni2++) {
        int col = ni2*8 + 2*tig;
        *(uint32_t*)(Obase + (size_t)r0*DI_ + col) = f2bf2(o[ni2][0]*i0, o[ni2][1]*i0);
        *(uint32_t*)(Obase + (size_t)r1*DI_ + col) = f2bf2(o[ni2][2]*i1, o[ni2][3]*i1);
    }
}

// ---------------- 5) deterministic scatter-mean combine ---------------------
__global__ void combine_kernel(const float* __restrict__ null_token, float* __restrict__ out)
{
    int bn = blockIdx.x;
    int b = bn / N_, n = bn % N_;
    int tid = threadIdx.x;
    float4 acc = make_float4(0,0,0,0);
    int cnt = 0;
    #pragma unroll
    for (int g = 0; g < G_; g++) {
        int s = g_slot[(size_t)(b*G_+g)*N_ + n];
        if (s >= 0) {
            cnt++;
            float4 v = ((const float4*)(g_of + ((size_t)(b*G_+g)*NQ_ + s)*D_))[tid];
            acc.x+=v.x; acc.y+=v.y; acc.z+=v.z; acc.w+=v.w;
        }
    }
    float4 o;
    if (cnt > 0) {
        float inv = 1.f/(float)cnt;
        o = make_float4(acc.x*inv, acc.y*inv, acc.z*inv, acc.w*inv);
    } else {
        o = ((const float4*)null_token)[tid];
    }
    ((float4*)out)[(size_t)bn*(D_/4) + tid] = o;
}

// ---------------- launch ----------------------------------------------------
extern "C" void kernel_launch(void* const* d_in, const int* in_sizes, int n_in,
                              void* d_out, int out_size)
{
    const float* x          = (const float*)d_in[0];
    const float* w_qr       = (const float*)d_in[1];
    const float* w_kvr      = (const float*)d_in[2];
    const float* w_q        = (const float*)d_in[3];
    const float* w_kv       = (const float*)d_in[4];
    const float* w_out      = (const float*)d_in[5];
    const float* null_kv    = (const float*)d_in[6];
    const float* null_token = (const float*)d_in[7];
    float* out = (float*)d_out;

    __nv_bfloat16 *p_xbf,*p_wqbf,*p_wkvbf,*p_woutbf,*p_q,*p_kv,*p_attno;
    float *p_qscore,*p_of;
    int *p_qidx,*p_kvidx;
    cudaGetSymbolAddress((void**)&p_xbf,    g_xbf);
    cudaGetSymbolAddress((void**)&p_wqbf,   g_wqbf);
    cudaGetSymbolAddress((void**)&p_wkvbf,  g_wkvbf);
    cudaGetSymbolAddress((void**)&p_woutbf, g_woutbf);
    cudaGetSymbolAddress((void**)&p_q,      g_q);
    cudaGetSymbolAddress((void**)&p_kv,     g_kv);
    cudaGetSymbolAddress((void**)&p_attno,  g_attno);
    cudaGetSymbolAddress((void**)&p_qscore, g_qscore);
    cudaGetSymbolAddress((void**)&p_of,     g_of);
    cudaGetSymbolAddress((void**)&p_qidx,   g_qidx);
    cudaGetSymbolAddress((void**)&p_kvidx,  g_kvidx);

    constexpr int BKP2 = 20;
    constexpr size_t GEMM_SMEM = (size_t)(3*128*BKP2 + 3*128*BKP2)*4 + 128*4;   // 61952
    constexpr size_t ATTN_SMEM = (size_t)(4*64*KR2)*4 + 2*64*4;                 // 37376

    static cudaStream_t s1 = nullptr;
    static cudaEvent_t evFork = nullptr, evCvt = nullptr, evTopk = nullptr;
    static cudaEvent_t evKv = nullptr, evQ1 = nullptr, evA0 = nullptr, evO0 = nullptr;
    static bool attr_done = false;
    if (!attr_done) {
        cudaFuncSetAttribute(mma_gemm<128,128,32,true,true>,
                             cudaFuncAttributeMaxDynamicSharedMemorySize, (int)GEMM_SMEM);
        cudaFuncSetAttribute(mma_gemm<128,128,32,false,false>,
                             cudaFuncAttributeMaxDynamicSharedMemorySize, (int)GEMM_SMEM);
        cudaFuncSetAttribute(attn_kernel,
                             cudaFuncAttributeMaxDynamicSharedMemorySize, (int)ATTN_SMEM);
        cudaStreamCreateWithFlags(&s1, cudaStreamNonBlocking);
        cudaEventCreateWithFlags(&evFork, cudaEventDisableTiming);
        cudaEventCreateWithFlags(&evCvt,  cudaEventDisableTiming);
        cudaEventCreateWithFlags(&evTopk, cudaEventDisableTiming);
        cudaEventCreateWithFlags(&evKv,   cudaEventDisableTiming);
        cudaEventCreateWithFlags(&evQ1,   cudaEventDisableTiming);
        cudaEventCreateWithFlags(&evA0,   cudaEventDisableTiming);
        cudaEventCreateWithFlags(&evO0,   cudaEventDisableTiming);
        attr_done = true;
    }

    const int HZ = B_*G_/2;   // 8 z-blocks per half

    // ---- fork -------------------------------------------------------------
    cudaEventRecord(evFork, 0);
    cudaStreamWaitEvent(s1, evFork, 0);

    // s1: weight conversion
    {
        int total4 = WQ4 + WKV4 + WOUT4 + NUL4;
        cvt_all<<<(total4 + 255)/256, 256, 0, s1>>>(w_q, w_kv, w_out, null_kv);
    }
    cudaEventRecord(evCvt, s1);

    // main: logits + topk
    logits_kernel<<<B_*N_/16, 512>>>(x, w_qr, w_kvr);
    topk_kernel<<<2*B_*G_, 1024>>>();
    cudaEventRecord(evTopk, 0);

    // s1: kv projection (full), then q projection half 1 (bg 8..15)
    cudaStreamWaitEvent(s1, evTopk, 0);
    {
        dim3 gr((2*DI_)/128, NK_/128, B_*G_);
        mma_gemm<128,128,32,true,true><<<gr,256,GEMM_SMEM,s1>>>(
            p_xbf, D_, G_, (long)N_*D_, 0L,
            p_wkvbf, D_, G_, 0L, (long)(2*DI_)*D_,
            p_kv, 2*DI_, 1, (long)NK_*2*DI_, 0L,
            D_, p_kvidx, NK_, nullptr, 0, 1.0f);
    }
    cudaEventRecord(evKv, s1);
    {   // qproj H1: z' = z+8 -> b += 2, g same; offset bases accordingly
        dim3 gr(DI_/128, NQ_/128, HZ);
        mma_gemm<128,128,32,true,true><<<gr,256,GEMM_SMEM,s1>>>(
            p_xbf + (size_t)2*N_*D_, D_, G_, (long)N_*D_, 0L,
            p_wqbf, D_, G_, 0L, (long)DI_*D_,
            p_q + (size_t)HZ*NQ_*DI_, DI_, 1, (long)NQ_*DI_, 0L,
            D_, p_qidx + HZ*NQ_, NQ_, nullptr, 0, 0.125f);
    }
    cudaEventRecord(evQ1, s1);

    // main: q projection half 0 (bg 0..7)
    cudaStreamWaitEvent(0, evCvt, 0);
    {
        dim3 gr(DI_/128, NQ_/128, HZ);
        mma_gemm<128,128,32,true,true><<<gr,256,GEMM_SMEM>>>(
            p_xbf, D_, G_, (long)N_*D_, 0L,
            p_wqbf, D_, G_, 0L, (long)DI_*D_,
            p_q, DI_, 1, (long)NQ_*DI_, 0L,
            D_, p_qidx, NQ_, nullptr, 0, 0.125f);
    }

    // main: attention half 0 (bgh 0..63) after kvproj
    cudaStreamWaitEvent(0, evKv, 0);
    {
        dim3 gr(NQ_/128, HZ*H_);
        attn_kernel<<<gr, 256, ATTN_SMEM>>>(0);
    }
    cudaEventRecord(evA0, 0);

    // s1: out projection half 0 (z 0..7) overlapping attention half 1
    cudaStreamWaitEvent(s1, evA0, 0);
    {
        dim3 gr(D_/128, NQ_/128, HZ);
        mma_gemm<128,128,32,false,false><<<gr,256,GEMM_SMEM,s1>>>(
            p_attno, DI_, 1, (long)NQ_*DI_, 0L,
            p_woutbf, DI_, G_, 0L, (long)D_*DI_,
            p_of, D_, 1, (long)NQ_*D_, 0L,
            DI_, nullptr, 0, p_qscore, NQ_, 1.0f);
    }
    cudaEventRecord(evO0, s1);

    // main: attention half 1 (bgh 64..127) after qproj H1
    cudaStreamWaitEvent(0, evQ1, 0);
    {
        dim3 gr(NQ_/128, HZ*H_);
        attn_kernel<<<gr, 256, ATTN_SMEM>>>(HZ*H_);
    }
    // main: out projection half 1 (z 8..15)
    {
        dim3 gr(D_/128, NQ_/128, HZ);
        mma_gemm<128,128,32,false,false><<<gr,256,GEMM_SMEM>>>(
            p_attno + (size_t)HZ*NQ_*DI_, DI_, 1, (long)NQ_*DI_, 0L,
            p_woutbf, DI_, G_, 0L, (long)D_*DI_,
            p_of + (size_t)HZ*NQ_*D_, D_, 1, (long)NQ_*D_, 0L,
            DI_, nullptr, 0, p_qscore + HZ*NQ_, NQ_, 1.0f);
    }
    // main: combine after both out-proj halves
    cudaStreamWaitEvent(0, evO0, 0);
    combine_kernel<<<B_*N_, 256>>>(null_token, out);
}

// round 12
// speedup vs baseline: 1.0626x; 1.0626x over previous
#include <cuda_runtime.h>
#include <cuda_bf16.h>
#include <cstdint>
#include <math.h>

#define B_ 4
#define N_ 4096
#define D_ 1024
#define G_ 4
#define H_ 8
#define DH_ 64
#define DI_ 512
#define NQ_ 1024
#define NK_ 512
#define NKV_ 513
#define NKVP_ 576

// ---------------- scratch ---------------------------------------------------
__device__ float         g_qlog [B_*G_*N_];
__device__ float         g_kvlog[B_*G_*N_];
__device__ int           g_qidx [B_*G_*NQ_];
__device__ float         g_qscore[B_*G_*NQ_];
__device__ int           g_kvidx [B_*G_*NK_];
__device__ float         g_sscale[B_*G_*NKVP_];
__device__ int           g_slot [B_*G_*N_];
__device__ __nv_bfloat16 g_xbf  [B_*N_*D_];
__device__ __nv_bfloat16 g_wqbf [G_*DI_*D_];
__device__ __nv_bfloat16 g_wkvbf[G_*2*DI_*D_];
__device__ __nv_bfloat16 g_woutbf[G_*D_*DI_];
__device__ __nv_bfloat16 g_nullbf[2*G_*H_*DH_];
__device__ __nv_bfloat16 g_q    [B_*G_*NQ_*DI_];
__device__ __nv_bfloat16 g_kv   [B_*G_*NK_*2*DI_];
__device__ __nv_bfloat16 g_attno[B_*G_*NQ_*DI_];
__device__ float         g_of   [(size_t)B_*G_*NQ_*D_];

// ---------------- helpers ---------------------------------------------------
__device__ __forceinline__ uint32_t f2bf2(float lo, float hi) {
    uint32_t r;
    asm("cvt.rn.bf16x2.f32 %0, %1, %2;" : "=r"(r) : "f"(hi), "f"(lo));
    return r;
}
__device__ __forceinline__ void mma_bf16(float c[4],
                                         uint32_t a0, uint32_t a1, uint32_t a2, uint32_t a3,
                                         uint32_t b0, uint32_t b1) {
    asm volatile(
        "mma.sync.aligned.m16n8k16.row.col.f32.bf16.bf16.f32 "
        "{%0,%1,%2,%3}, {%4,%5,%6,%7}, {%8,%9}, {%0,%1,%2,%3};\n"
        : "+f"(c[0]), "+f"(c[1]), "+f"(c[2]), "+f"(c[3])
        : "r"(a0), "r"(a1), "r"(a2), "r"(a3), "r"(b0), "r"(b1));
}
__device__ __forceinline__ void ldsm_x4(uint32_t& r0, uint32_t& r1, uint32_t& r2, uint32_t& r3,
                                        uint32_t addr) {
    asm volatile("ldmatrix.sync.aligned.m8n8.x4.shared.b16 {%0,%1,%2,%3}, [%4];"
                 : "=r"(r0), "=r"(r1), "=r"(r2), "=r"(r3) : "r"(addr));
}
__device__ __forceinline__ void ldsm_x4_t(uint32_t& r0, uint32_t& r1, uint32_t& r2, uint32_t& r3,
                                          uint32_t addr) {
    asm volatile("ldmatrix.sync.aligned.m8n8.x4.trans.shared.b16 {%0,%1,%2,%3}, [%4];"
                 : "=r"(r0), "=r"(r1), "=r"(r2), "=r"(r3) : "r"(addr));
}
__device__ __forceinline__ void cp_async16(void* smem_dst, const void* gmem_src) {
    uint32_t s = (uint32_t)__cvta_generic_to_shared(smem_dst);
    asm volatile("cp.async.cg.shared.global [%0], [%1], 16;\n" :: "r"(s), "l"(gmem_src));
}
__device__ __forceinline__ void cp_commit() { asm volatile("cp.async.commit_group;\n"); }
__device__ __forceinline__ void cp_wait0() { asm volatile("cp.async.wait_group 0;\n"); }
__device__ __forceinline__ void cp_wait1() { asm volatile("cp.async.wait_group 1;\n"); }

// ---------------- 0) fp32 -> bf16 convert (weights + null_kv) ---------------
#define WQ4   (G_*DI_*D_/4)
#define WKV4  (G_*2*DI_*D_/4)
#define WOUT4 (G_*D_*DI_/4)
#define NUL4  (2*G_*H_*DH_/4)
__device__ __forceinline__ void cvt4(const float* s, __nv_bfloat16* d, int i) {
    float4 v = ((const float4*)s)[i];
    ((uint2*)d)[i] = make_uint2(f2bf2(v.x, v.y), f2bf2(v.z, v.w));
}
__global__ void cvt_all(const float* __restrict__ wq, const float* __restrict__ wkv,
                        const float* __restrict__ wout, const float* __restrict__ nul)
{
    int i = blockIdx.x*256 + threadIdx.x;
    if (i < WQ4) { cvt4(wq, g_wqbf, i); return; }
    i -= WQ4;
    if (i < WKV4) { cvt4(wkv, g_wkvbf, i); return; }
    i -= WKV4;
    if (i < WOUT4) { cvt4(wout, g_woutbf, i); return; }
    i -= WOUT4;
    if (i < NUL4) cvt4(nul, g_nullbf, i);
}

// ---------------- 1) router logits (fp32) + x -> bf16 -----------------------
__global__ void __launch_bounds__(512) logits_kernel(const float* __restrict__ x,
                                                     const float* __restrict__ w_qr,
                                                     const float* __restrict__ w_kvr)
{
    __shared__ float ws[8*D_];
    int tid = threadIdx.x;
    for (int i = tid; i < 4*D_; i += 512) { ws[i] = w_qr[i]; ws[4*D_+i] = w_kvr[i]; }
    __syncthreads();
    int warp = tid >> 5, lane = tid & 31;
    int tok = blockIdx.x*16 + warp;
    int b = tok / N_, n = tok % N_;
    const float4* xr = (const float4*)(x + (size_t)tok*D_);
    uint2* xt = (uint2*)(g_xbf + (size_t)tok*D_);
    float acc[8] = {0,0,0,0,0,0,0,0};
    #pragma unroll
    for (int it = 0; it < 8; it++) {
        int k4 = lane + it*32;
        float4 xv = xr[k4];
        xt[k4] = make_uint2(f2bf2(xv.x, xv.y), f2bf2(xv.z, xv.w));
        #pragma unroll
        for (int g = 0; g < 8; g++) {
            float4 w4 = *(const float4*)(ws + g*D_ + k4*4);   // LDS.128, conflict-free
            acc[g] += xv.x*w4.x + xv.y*w4.y + xv.z*w4.z + xv.w*w4.w;
        }
    }
    #pragma unroll
    for (int g = 0; g < 8; g++) {
        #pragma unroll
        for (int o = 16; o > 0; o >>= 1) acc[g] += __shfl_xor_sync(0xffffffffu, acc[g], o);
    }
    if (lane < 4) {
        g_qlog[(b*G_+lane)*N_ + n] = acc[lane];
        g_slot[(b*G_+lane)*N_ + n] = -1;
    } else if (lane < 8) {
        g_kvlog[(b*G_+(lane-4))*N_ + n] = acc[lane];
    }
}

// ---------------- 2) exact top-k via per-(b,g) bitonic sort (q + kv) --------
__global__ void topk_kernel()
{
    __shared__ float sv[N_];
    __shared__ int   si[N_];
    const bool isq = blockIdx.x < (B_*G_);
    const int bg = isq ? blockIdx.x : blockIdx.x - B_*G_;
    const int ksel = isq ? NQ_ : NK_;
    const float* L = (isq ? g_qlog : g_kvlog) + (size_t)bg*N_;
    for (int i = threadIdx.x; i < N_; i += blockDim.x) { sv[i]=L[i]; si[i]=i; }
    __syncthreads();
    for (int k = 2; k <= N_; k <<= 1) {
        for (int j = k>>1; j > 0; j >>= 1) {
            for (int t = threadIdx.x; t < N_/2; t += blockDim.x) {
                int i = ((t / j) * (2*j)) + (t % j);
                int p = i | j;
                bool descend = ((i & k) == 0);
                float va = sv[i], vb = sv[p];
                int   ia = si[i], ib = si[p];
                bool agtb = (va > vb) || (va == vb && ia < ib);
                if (agtb != descend) { sv[i]=vb; si[i]=ib; sv[p]=va; si[p]=ia; }
            }
            __syncthreads();
        }
    }
    if (isq) {
        for (int i = threadIdx.x; i < ksel; i += blockDim.x) {
            int id = si[i];
            g_qidx[bg*ksel + i]   = id;
            g_qscore[bg*ksel + i] = 1.0f/(1.0f + expf(-sv[i]));
            g_slot[(size_t)bg*N_ + id] = i;
        }
    } else {
        for (int i = threadIdx.x; i < ksel; i += blockDim.x) {
            g_kvidx[bg*ksel + i] = si[i];
            g_sscale[bg*NKVP_ + 1 + i] = 1.0f/(1.0f + expf(-sv[i]));
        }
        if (threadIdx.x == 0) g_sscale[bg*NKVP_] = 1.0f;
        for (int i = NKV_ + threadIdx.x; i < NKVP_; i += blockDim.x)
            g_sscale[bg*NKVP_ + i] = 1.0f;
    }
}

// ---------------- 3) 3-stage bf16 GEMM, ONE sync per chunk ------------------
// BM=128, BN=128, BK=32(bf16), 8 warps (2x4), warp tile 64x32, ldmatrix frags.
// Loop order: wait -> sync -> prefetch(j+2) -> compute  (single barrier).
template<int BM,int BN,int BK,bool GATHER,bool OUT_BF16>
__global__ void __launch_bounds__(256, 2)
mma_gemm(const __nv_bfloat16* __restrict__ A, int lda, int zdivA, long sA1, long sA2,
         const __nv_bfloat16* __restrict__ Bp, int ldb, int zdivB, long sB1, long sB2,
         void* __restrict__ Cv, int ldc, int zdivC, long sC1, long sC2,
         int K,
         const int* __restrict__ gidx, int gstride,
         const float* __restrict__ rowScale, int rsStride,
         float cscale)
{
    constexpr int WM = BM/2, WN = BN/4;      // 64, 32
    constexpr int MI = WM/16, NI = WN/8;     // 4, 4
    constexpr int BKP2 = BK/2 + 4;           // 20 b32 row stride
    constexpr int ASTG = BM*BKP2, BSTG = BN*BKP2;

    extern __shared__ uint32_t dsm[];
    uint32_t* Asf = dsm;                      // 3 stages
    uint32_t* Bsf = dsm + 3*ASTG;
    int*      ridx = (int*)(dsm + 3*ASTG + 3*BSTG);

    const int z = blockIdx.z;
    A  += (long)(z/zdivA)*sA1 + (long)(z%zdivA)*sA2;
    Bp += (long)(z/zdivB)*sB1 + (long)(z%zdivB)*sB2;
    const int m0 = blockIdx.y*BM, n0 = blockIdx.x*BN;
    const int tid  = threadIdx.x;
    const int warp = tid >> 5, lane = tid & 31;
    const int gid  = lane >> 2, tig = lane & 3;
    const int wm0  = (warp >> 2) * WM;
    const int wn0  = (warp & 3) * WN;

    if (GATHER) {
        for (int i = tid; i < BM; i += 256) ridx[i] = gidx[z*gstride + m0 + i];
        __syncthreads();
    }

    auto prefetch = [&](int k0, int s) {
        uint32_t* As_ = Asf + s*ASTG;
        #pragma unroll
        for (int f = tid; f < BM*(BK/8); f += 256) {
            int m = f / (BK/8), c = f % (BK/8);
            long row = GATHER ? (long)ridx[m] : (long)(m0+m);
            cp_async16(&As_[m*BKP2 + c*4], A + row*(long)lda + k0 + c*8);
        }
        uint32_t* Bs_ = Bsf + s*BSTG;
        #pragma unroll
        for (int f = tid; f < BN*(BK/8); f += 256) {
            int nn = f / (BK/8), c = f % (BK/8);
            cp_async16(&Bs_[nn*BKP2 + c*4], Bp + (long)(n0+nn)*ldb + k0 + c*8);
        }
        cp_commit();
    };

    float acc[MI][NI][4];
    #pragma unroll
    for (int mi=0;mi<MI;mi++)
        #pragma unroll
        for (int ni=0;ni<NI;ni++)
            #pragma unroll
            for (int r=0;r<4;r++) acc[mi][ni][r] = 0.f;

    const uint32_t AsA = (uint32_t)__cvta_generic_to_shared(Asf);
    const uint32_t BsA = (uint32_t)__cvta_generic_to_shared(Bsf);
    const int lm = lane >> 3, lr = lane & 7;
    const uint32_t aLane = (uint32_t)(((wm0 + (lm&1)*8 + lr)*BKP2 + (lm>>1)*4) * 4);
    const uint32_t bLane = (uint32_t)(((wn0 + (lm>>1)*8 + lr)*BKP2 + (lm&1)*4) * 4);

    const int NKIT = K / BK;
    prefetch(0, 0);
    if (NKIT > 1) prefetch(BK, 1);
    for (int j = 0; j < NKIT; j++) {
        if (j + 1 < NKIT) cp_wait1(); else cp_wait0();
        __syncthreads();                               // data j visible; stage (j-1)%3 free
        if (j + 2 < NKIT) prefetch((j+2)*BK, (j+2)%3);

        const uint32_t AsJ = AsA + (uint32_t)((j%3)*ASTG*4) + aLane;
        const uint32_t BsJ = BsA + (uint32_t)((j%3)*BSTG*4) + bLane;
        #pragma unroll
        for (int kk = 0; kk < BK/16; kk++) {
            uint32_t a[MI][4];
            uint32_t b[NI][2];
            #pragma unroll
            for (int mi=0;mi<MI;mi++)
                ldsm_x4(a[mi][0], a[mi][1], a[mi][2], a[mi][3],
                        AsJ + (uint32_t)(mi*16*BKP2*4 + kk*32));
            #pragma unroll
            for (int nip=0;nip<NI/2;nip++)
                ldsm_x4(b[2*nip][0], b[2*nip][1], b[2*nip+1][0], b[2*nip+1][1],
                        BsJ + (uint32_t)(nip*16*BKP2*4 + kk*32));
            #pragma unroll
            for (int mi=0;mi<MI;mi++)
                #pragma unroll
                for (int ni=0;ni<NI;ni++)
                    mma_bf16(acc[mi][ni], a[mi][0], a[mi][1], a[mi][2], a[mi][3],
                             b[ni][0], b[ni][1]);
        }
    }

    #pragma unroll
    for (int mi=0;mi<MI;mi++) {
        int r0 = m0 + wm0 + mi*16 + gid;
        int r1 = r0 + 8;
        float rs0 = cscale, rs1 = cscale;
        if (rowScale) {
            rs0 *= rowScale[z*rsStride + r0];
            rs1 *= rowScale[z*rsStride + r1];
        }
        #pragma unroll
        for (int ni=0;ni<NI;ni++) {
            int ccol = n0 + wn0 + ni*8 + tig*2;
            if (OUT_BF16) {
                uint32_t* Cb = (uint32_t*)Cv + ((long)(z/zdivC)*sC1 + (long)(z%zdivC)*sC2)/2;
                Cb[((long)r0*ldc + ccol) >> 1] = f2bf2(acc[mi][ni][0]*rs0, acc[mi][ni][1]*rs0);
                Cb[((long)r1*ldc + ccol) >> 1] = f2bf2(acc[mi][ni][2]*rs1, acc[mi][ni][3]*rs1);
            } else {
                float* C = (float*)Cv + (long)(z/zdivC)*sC1 + (long)(z%zdivC)*sC2;
                *(float2*)(C + (long)r0*ldc + ccol) =
                    make_float2(acc[mi][ni][0]*rs0, acc[mi][ni][1]*rs0);
                *(float2*)(C + (long)r1*ldc + ccol) =
                    make_float2(acc[mi][ni][2]*rs1, acc[mi][ni][3]*rs1);
            }
        }
    }
}

// ---------------- 4) fused flash attention: 3-stage, one sync per chunk -----
#define KR2 36
#define NCH 9
__global__ void __launch_bounds__(256) attn_kernel()
{
    extern __shared__ uint32_t smem[];
    uint32_t* Ks = smem;                        // 3 stages [64][KR2]
    uint32_t* Vs = smem + 3*64*KR2;             // 3 stages [64][KR2]
    float*    Ss = (float*)(smem + 6*64*KR2);   // 3 stages [64]

    const int bgh = blockIdx.y;
    const int bg = bgh >> 3, h = bgh & 7;
    const int g  = bg & 3;
    const int m0q = blockIdx.x * 128;
    const int tid = threadIdx.x, warp = tid >> 5, lane = tid & 31;
    const int gid = lane >> 2, tig = lane & 3;
    const int wm = warp * 16;

    const __nv_bfloat16* Qbase = g_q + (size_t)bg*NQ_*DI_ + h*DH_;
    const __nv_bfloat16* KVb   = g_kv + (size_t)bg*NK_*2*DI_ + h*DH_;
    const __nv_bfloat16* nulK  = g_nullbf + ((0*G_+g)*H_ + h)*DH_;
    const __nv_bfloat16* nulV  = g_nullbf + ((1*G_+g)*H_ + h)*DH_;
    const float*         Sg    = g_sscale + bg*NKVP_;

    const int r0 = m0q + wm + gid, r1 = r0 + 8;

    auto prefetch = [&](int ch, int s) {
        const int j0 = ch * 64;
        uint32_t* Kd = Ks + s*64*KR2;
        uint32_t* Vd = Vs + s*64*KR2;
        #pragma unroll
        for (int f = tid; f < 64*8; f += 256) {
            int r = f >> 3, c = (f & 7) * 8;
            int j = j0 + r;
            if (j == 0) {
                cp_async16(&Kd[r*KR2 + c/2], nulK + c);
                cp_async16(&Vd[r*KR2 + c/2], nulV + c);
            } else {
                int jj = (j-1 < NK_-1) ? (j-1) : (NK_-1);
                const __nv_bfloat16* base = KVb + (size_t)jj*(2*DI_) + c;
                cp_async16(&Kd[r*KR2 + c/2], base);
                cp_async16(&Vd[r*KR2 + c/2], base + DI_);
            }
        }
        if (tid < 16) cp_async16(&Ss[s*64 + tid*4], Sg + j0 + tid*4);
        cp_commit();
    };

    uint32_t aQ[4][4];
    #pragma unroll
    for (int kk = 0; kk < 4; kk++) {
        aQ[kk][0] = *(const uint32_t*)(Qbase + (size_t)r0*DI_ + kk*16 + 2*tig    );
        aQ[kk][1] = *(const uint32_t*)(Qbase + (size_t)r1*DI_ + kk*16 + 2*tig    );
        aQ[kk][2] = *(const uint32_t*)(Qbase + (size_t)r0*DI_ + kk*16 + 2*tig + 8);
        aQ[kk][3] = *(const uint32_t*)(Qbase + (size_t)r1*DI_ + kk*16 + 2*tig + 8);
    }

    const int lm = lane >> 3, lr = lane & 7;
    const uint32_t kLane = (uint32_t)((((lm>>1)*8 + lr)*KR2 + (lm&1)*4) * 4);
    const uint32_t vLane = (uint32_t)(((lm & 1)*8 + lr) * (KR2*4) + (lm >> 1)*16);
    const uint32_t KsA = (uint32_t)__cvta_generic_to_shared(Ks);
    const uint32_t VsA = (uint32_t)__cvta_generic_to_shared(Vs);

    float o[8][4];
    #pragma unroll
    for (int i=0;i<8;i++) { o[i][0]=0.f; o[i][1]=0.f; o[i][2]=0.f; o[i][3]=0.f; }
    float l0 = 0.f, l1 = 0.f;

    prefetch(0, 0);
    prefetch(1, 1);
    for (int ch = 0; ch < NCH; ch++) {
        const int s = ch % 3;
        const int j0 = ch * 64;
        if (ch + 1 < NCH) cp_wait1(); else cp_wait0();
        __syncthreads();                            // data ch visible; stage (ch-1)%3 free
        if (ch + 2 < NCH) prefetch(ch + 2, (ch + 2) % 3);

        const uint32_t KcA = KsA + (uint32_t)(s*64*KR2*4) + kLane;
        const uint32_t VcA = VsA + (uint32_t)(s*64*KR2*4) + vLane;
        const float*   sc  = Ss + s*64;

        float sfr[8][4];
        #pragma unroll
        for (int i=0;i<8;i++){ sfr[i][0]=0.f; sfr[i][1]=0.f; sfr[i][2]=0.f; sfr[i][3]=0.f; }
        #pragma unroll
        for (int kk = 0; kk < 4; kk++) {
            #pragma unroll
            for (int nip = 0; nip < 4; nip++) {
                uint32_t b0, b1, b2, b3;
                ldsm_x4(b0, b1, b2, b3, KcA + (uint32_t)(nip*16*KR2*4 + kk*32));
                mma_bf16(sfr[2*nip  ], aQ[kk][0], aQ[kk][1], aQ[kk][2], aQ[kk][3], b0, b1);
                mma_bf16(sfr[2*nip+1], aQ[kk][0], aQ[kk][1], aQ[kk][2], aQ[kk][3], b2, b3);
            }
        }
        if (ch == NCH-1) {
            #pragma unroll
            for (int ni = 0; ni < 8; ni++) {
                int j = j0 + ni*8 + 2*tig;
                if (j   > 512) { sfr[ni][0] = -1e30f; sfr[ni][2] = -1e30f; }
                if (j+1 > 512) { sfr[ni][1] = -1e30f; sfr[ni][3] = -1e30f; }
            }
        }
        #pragma unroll
        for (int ni = 0; ni < 8; ni++) {
            sfr[ni][0] = __expf(sfr[ni][0]);
            sfr[ni][1] = __expf(sfr[ni][1]);
            sfr[ni][2] = __expf(sfr[ni][2]);
            sfr[ni][3] = __expf(sfr[ni][3]);
            l0 += sfr[ni][0] + sfr[ni][1];
            l1 += sfr[ni][2] + sfr[ni][3];
        }
        #pragma unroll
        for (int kk = 0; kk < 4; kk++) {
            float2 sA = *(const float2*)&sc[kk*16 + 2*tig    ];
            float2 sB = *(const float2*)&sc[kk*16 + 2*tig + 8];
            uint32_t aP0 = f2bf2(sfr[2*kk  ][0]*sA.x, sfr[2*kk  ][1]*sA.y);
            uint32_t aP1 = f2bf2(sfr[2*kk  ][2]*sA.x, sfr[2*kk  ][3]*sA.y);
            uint32_t aP2 = f2bf2(sfr[2*kk+1][0]*sB.x, sfr[2*kk+1][1]*sB.y);
            uint32_t aP3 = f2bf2(sfr[2*kk+1][2]*sB.x, sfr[2*kk+1][3]*sB.y);
            #pragma unroll
            for (int np = 0; np < 4; np++) {
                uint32_t v0, v1, v2, v3;
                ldsm_x4_t(v0, v1, v2, v3, VcA + (uint32_t)(kk*16*(KR2*4) + np*32));
                mma_bf16(o[2*np  ], aP0, aP1, aP2, aP3, v0, v1);
                mma_bf16(o[2*np+1], aP0, aP1, aP2, aP3, v2, v3);
            }
        }
    }

    l0 += __shfl_xor_sync(0xffffffffu, l0, 1);
    l0 += __shfl_xor_sync(0xffffffffu, l0, 2);
    l1 += __shfl_xor_sync(0xffffffffu, l1, 1);
    l1 += __shfl_xor_sync(0xffffffffu, l1, 2);
    float i0 = 1.f/l0, i1 = 1.f/l1;
    __nv_bfloat16* Obase = g_attno + (size_t)bg*NQ_*DI_ + h*DH_;
    #pragma unroll
    for (int ni2 = 0; ni2 < 8; ni2++) {
        int col = ni2*8 + 2*tig;
        *(uint32_t*)(Obase + (size_t)r0*DI_ + col) = f2bf2(o[ni2][0]*i0, o[ni2][1]*i0);
        *(uint32_t*)(Obase + (size_t)r1*DI_ + col) = f2bf2(o[ni2][2]*i1, o[ni2][3]*i1);
    }
}

// ---------------- 5) deterministic scatter-mean combine ---------------------
__global__ void combine_kernel(const float* __restrict__ null_token, float* __restrict__ out)
{
    int bn = blockIdx.x;
    int b = bn / N_, n = bn % N_;
    int tid = threadIdx.x;
    float4 acc = make_float4(0,0,0,0);
    int cnt = 0;
    #pragma unroll
    for (int g = 0; g < G_; g++) {
        int s = g_slot[(size_t)(b*G_+g)*N_ + n];
        if (s >= 0) {
            cnt++;
            float4 v = ((const float4*)(g_of + ((size_t)(b*G_+g)*NQ_ + s)*D_))[tid];
            acc.x+=v.x; acc.y+=v.y; acc.z+=v.z; acc.w+=v.w;
        }
    }
    float4 o;
    if (cnt > 0) {
        float inv = 1.f/(float)cnt;
        o = make_float4(acc.x*inv, acc.y*inv, acc.z*inv, acc.w*inv);
    } else {
        o = ((const float4*)null_token)[tid];
    }
    ((float4*)out)[(size_t)bn*(D_/4) + tid] = o;
}

// ---------------- launch ----------------------------------------------------
extern "C" void kernel_launch(void* const* d_in, const int* in_sizes, int n_in,
                              void* d_out, int out_size)
{
    const float* x          = (const float*)d_in[0];
    const float* w_qr       = (const float*)d_in[1];
    const float* w_kvr      = (const float*)d_in[2];
    const float* w_q        = (const float*)d_in[3];
    const float* w_kv       = (const float*)d_in[4];
    const float* w_out      = (const float*)d_in[5];
    const float* null_kv    = (const float*)d_in[6];
    const float* null_token = (const float*)d_in[7];
    float* out = (float*)d_out;

    __nv_bfloat16 *p_xbf,*p_wqbf,*p_wkvbf,*p_woutbf,*p_q,*p_kv,*p_attno;
    float *p_qscore,*p_of;
    int *p_qidx,*p_kvidx;
    cudaGetSymbolAddress((void**)&p_xbf,    g_xbf);
    cudaGetSymbolAddress((void**)&p_wqbf,   g_wqbf);
    cudaGetSymbolAddress((void**)&p_wkvbf,  g_wkvbf);
    cudaGetSymbolAddress((void**)&p_woutbf, g_woutbf);
    cudaGetSymbolAddress((void**)&p_q,      g_q);
    cudaGetSymbolAddress((void**)&p_kv,     g_kv);
    cudaGetSymbolAddress((void**)&p_attno,  g_attno);
    cudaGetSymbolAddress((void**)&p_qscore, g_qscore);
    cudaGetSymbolAddress((void**)&p_of,     g_of);
    cudaGetSymbolAddress((void**)&p_qidx,   g_qidx);
    cudaGetSymbolAddress((void**)&p_kvidx,  g_kvidx);

    constexpr int BKP2 = 20;
    constexpr size_t GEMM_SMEM = (size_t)(3*128*BKP2 + 3*128*BKP2)*4 + 128*4;   // 61952
    constexpr size_t ATTN_SMEM = (size_t)(6*64*KR2)*4 + 3*64*4;                 // 56064

    static cudaStream_t s1 = nullptr;
    static cudaEvent_t evFork = nullptr, evCvt = nullptr, evTopk = nullptr, evKv = nullptr;
    static bool attr_done = false;
    if (!attr_done) {
        cudaFuncSetAttribute(mma_gemm<128,128,32,true,true>,
                             cudaFuncAttributeMaxDynamicSharedMemorySize, (int)GEMM_SMEM);
        cudaFuncSetAttribute(mma_gemm<128,128,32,false,false>,
                             cudaFuncAttributeMaxDynamicSharedMemorySize, (int)GEMM_SMEM);
        cudaFuncSetAttribute(attn_kernel,
                             cudaFuncAttributeMaxDynamicSharedMemorySize, (int)ATTN_SMEM);
        cudaStreamCreateWithFlags(&s1, cudaStreamNonBlocking);
        cudaEventCreateWithFlags(&evFork, cudaEventDisableTiming);
        cudaEventCreateWithFlags(&evCvt,  cudaEventDisableTiming);
        cudaEventCreateWithFlags(&evTopk, cudaEventDisableTiming);
        cudaEventCreateWithFlags(&evKv,   cudaEventDisableTiming);
        attr_done = true;
    }

    // fork: s1 converts weights while main does logits+topk
    cudaEventRecord(evFork, 0);
    cudaStreamWaitEvent(s1, evFork, 0);
    {
        int total4 = WQ4 + WKV4 + WOUT4 + NUL4;
        cvt_all<<<(total4 + 255)/256, 256, 0, s1>>>(w_q, w_kv, w_out, null_kv);
    }
    cudaEventRecord(evCvt, s1);

    logits_kernel<<<B_*N_/16, 512>>>(x, w_qr, w_kvr);
    topk_kernel<<<2*B_*G_, 1024>>>();
    cudaEventRecord(evTopk, 0);

    // s1: kv projection
    cudaStreamWaitEvent(s1, evTopk, 0);
    {
        dim3 gr((2*DI_)/128, NK_/128, B_*G_);
        mma_gemm<128,128,32,true,true><<<gr,256,GEMM_SMEM,s1>>>(
            p_xbf, D_, G_, (long)N_*D_, 0L,
            p_wkvbf, D_, G_, 0L, (long)(2*DI_)*D_,
            p_kv, 2*DI_, 1, (long)NK_*2*DI_, 0L,
            D_, p_kvidx, NK_, nullptr, 0, 1.0f);
    }
    cudaEventRecord(evKv, s1);

    // main: q projection (DH^-0.5 fused into output scale)
    cudaStreamWaitEvent(0, evCvt, 0);
    {
        dim3 gr(DI_/128, NQ_/128, B_*G_);
        mma_gemm<128,128,32,true,true><<<gr,256,GEMM_SMEM>>>(
            p_xbf, D_, G_, (long)N_*D_, 0L,
            p_wqbf, D_, G_, 0L, (long)DI_*D_,
            p_q, DI_, 1, (long)NQ_*DI_, 0L,
            D_, p_qidx, NQ_, nullptr, 0, 0.125f);
    }

    // join -> attention
    cudaStreamWaitEvent(0, evKv, 0);
    {
        dim3 gr(NQ_/128, B_*G_*H_);
        attn_kernel<<<gr, 256, ATTN_SMEM>>>();
    }
    // out projection + q_score row scaling (fp32 out)
    {
        dim3 gr(D_/128, NQ_/128, B_*G_);
        mma_gemm<128,128,32,false,false><<<gr,256,GEMM_SMEM>>>(
            p_attno, DI_, 1, (long)NQ_*DI_, 0L,
            p_woutbf, DI_, G_, 0L, (long)D_*DI_,
            p_of, D_, 1, (long)NQ_*D_, 0L,
            DI_, nullptr, 0, p_qscore, NQ_, 1.0f);
    }
    combine_kernel<<<B_*N_, 256>>>(null_token, out);
}